// round 6
// baseline (speedup 1.0000x reference)
#include <cuda_runtime.h>
#include <math.h>

// Problem constants (fixed by reference setup_inputs)
#define NB 32
#define BV 516
#define NS 2048
#define NROWS (NB * BV)     // 16512 (b,v) rows
#define NCOLS (NB * NS)     // 65536 (b,s) columns
#define TPB 128
#define NVCHUNK 4
#define VCHUNK 129          // 516 / 4
#define NSCHUNK (NS / TPB)  // 16 s-chunks
#define NBLKC (NCOLS / TPB) // 512 comb blocks
#define NEG_BIG (-1e30f)

// Scratch (no allocations allowed -> __device__ globals)
__device__ float  g_rowpart[NSCHUNK * NROWS];     // per-(s-chunk) row partial sums
__device__ float  g_lse[NROWS];
__device__ float  g_delta[NB];
__device__ float  g_psum[NVCHUNK * NCOLS];        // per-chunk column sum of exp
__device__ float4 g_cval[NVCHUNK * NCOLS];        // top-4 values per chunk-column
__device__ uchar4 g_cidx[NVCHUNK * NCOLS];        // their local v indices (0..128)
__device__ double g_part_nll[NBLKC];
__device__ double g_part_mask[NBLKC];
__device__ unsigned int g_arrive;                  // zero-init; reset each run

// ---------------------------------------------------------------------------
// Kernel 1 (the ONLY full read of the tensor): per (s-chunk, b, v-chunk) block.
// Produces: per-column sum of exp, per-row partial sums (seq-softmax input),
// and exact top-4 (value,index) argmax candidates per chunk-column.
// ---------------------------------------------------------------------------
__global__ void __launch_bounds__(TPB) k_main(const float* __restrict__ out) {
    const int sc = blockIdx.x;
    const int b  = blockIdx.y;
    const int c  = blockIdx.z;
    const int v0 = c * VCHUNK;
    const int t  = threadIdx.x;
    const int lane = t & 31, w = t >> 5;
    const int s = sc * TPB + t;

    const float* col = out + ((size_t)b * BV + v0) * NS + s;

    __shared__ float sh4[VCHUNK][4];   // per-warp row partials

    float csum = 0.0f;
    float c0 = NEG_BIG, c1 = NEG_BIG, c2 = NEG_BIG, c3 = NEG_BIG;
    int   i0 = 0, i1 = 0, i2 = 0, i3 = 0;

    #pragma unroll 1
    for (int v = 0; v < 128; v += 8) {
        float x[8];
        #pragma unroll
        for (int j = 0; j < 8; j++)
            x[j] = __ldg(col + (size_t)(v + j) * NS);
        #pragma unroll
        for (int j = 0; j < 8; j++) {
            const float e = __expf(x[j]);
            csum += e;
            // warp-sum of e -> per-warp row partial
            float r = e;
            r += __shfl_down_sync(0xffffffffu, r, 16);
            r += __shfl_down_sync(0xffffffffu, r, 8);
            r += __shfl_down_sync(0xffffffffu, r, 4);
            r += __shfl_down_sync(0xffffffffu, r, 2);
            r += __shfl_down_sync(0xffffffffu, r, 1);
            if (lane == 0) sh4[v + j][w] = r;
            // sorted top-4 insert (c0 >= c1 >= c2 >= c3)
            const float xx = x[j];
            if (xx > c3) {
                c3 = xx; i3 = v + j;
                if (c3 > c2) { float tf = c2; c2 = c3; c3 = tf; int ti = i2; i2 = i3; i3 = ti; }
                if (c2 > c1) { float tf = c1; c1 = c2; c2 = tf; int ti = i1; i1 = i2; i2 = ti; }
                if (c1 > c0) { float tf = c0; c0 = c1; c1 = tf; int ti = i0; i0 = i1; i1 = ti; }
            }
        }
    }
    {   // remainder row v = 128 (129th)
        const float xx = __ldg(col + (size_t)128 * NS);
        const float e = __expf(xx);
        csum += e;
        float r = e;
        r += __shfl_down_sync(0xffffffffu, r, 16);
        r += __shfl_down_sync(0xffffffffu, r, 8);
        r += __shfl_down_sync(0xffffffffu, r, 4);
        r += __shfl_down_sync(0xffffffffu, r, 2);
        r += __shfl_down_sync(0xffffffffu, r, 1);
        if (lane == 0) sh4[128][w] = r;
        if (xx > c3) {
            c3 = xx; i3 = 128;
            if (c3 > c2) { float tf = c2; c2 = c3; c3 = tf; int ti = i2; i2 = i3; i3 = ti; }
            if (c2 > c1) { float tf = c1; c1 = c2; c2 = tf; int ti = i1; i1 = i2; i2 = ti; }
            if (c1 > c0) { float tf = c0; c0 = c1; c1 = tf; int ti = i0; i0 = i1; i1 = ti; }
        }
    }
    __syncthreads();

    // fixed-order combine of per-warp row partials -> global (deterministic)
    for (int i = t; i < VCHUNK; i += TPB) {
        const float r = ((sh4[i][0] + sh4[i][1]) + sh4[i][2]) + sh4[i][3];
        g_rowpart[sc * NROWS + b * BV + v0 + i] = r;
    }

    const int n = b * NS + s;
    g_psum[c * NCOLS + n] = csum;
    g_cval[c * NCOLS + n] = make_float4(c0, c1, c2, c3);
    g_cidx[c * NCOLS + n] = make_uchar4((unsigned char)i0, (unsigned char)i1,
                                        (unsigned char)i2, (unsigned char)i3);
}

// ---------------------------------------------------------------------------
// Kernel 2 (tiny): reduce 16 s-chunk partials per row (fixed order) -> lse,
// plus per-batch lse spread Delta_b.
// ---------------------------------------------------------------------------
__global__ void __launch_bounds__(512) k_lse(void) {
    const int b = blockIdx.x;
    const int t = threadIdx.x;
    float lmin = 1e30f, lmax = NEG_BIG;

    for (int v = t; v < BV; v += 512) {
        float ssum = 0.0f;
        #pragma unroll
        for (int sc = 0; sc < NSCHUNK; sc++)
            ssum += g_rowpart[sc * NROWS + b * BV + v];
        const float l = __logf(ssum);
        g_lse[b * BV + v] = l;
        lmin = fminf(lmin, l);
        lmax = fmaxf(lmax, l);
    }
    #pragma unroll
    for (int o = 16; o; o >>= 1) {
        lmin = fminf(lmin, __shfl_down_sync(0xffffffffu, lmin, o));
        lmax = fmaxf(lmax, __shfl_down_sync(0xffffffffu, lmax, o));
    }
    __shared__ float smin[16], smax[16];
    if ((t & 31) == 0) { smin[t >> 5] = lmin; smax[t >> 5] = lmax; }
    __syncthreads();
    if (t == 0) {
        float mn = smin[0], mx = smax[0];
        #pragma unroll
        for (int i = 1; i < 16; i++) { mn = fminf(mn, smin[i]); mx = fmaxf(mx, smax[i]); }
        g_delta[b] = mx - mn;
    }
}

// ---------------------------------------------------------------------------
// Kernel 3: per column -> nll from colsum, argmax from candidates (provably
// exact when every chunk's 4th value < m - Delta_b; else re-read the column),
// penalty mask, deterministic reduction, fused last-block finalize.
// ---------------------------------------------------------------------------
__global__ void __launch_bounds__(TPB) k_comb(
    const float* __restrict__ out,
    const int*   __restrict__ target,
    const int*   __restrict__ ttype,
    const float* __restrict__ tvalue,
    const float* __restrict__ coeff,
    const float* __restrict__ harm,
    float*       __restrict__ res)
{
    const int n = blockIdx.x * TPB + threadIdx.x;   // 0..65535
    const int b = n >> 11;
    const int s = n & (NS - 1);
    const float* lse = g_lse + b * BV;

    float csum = 0.0f;
    float4 cv[NVCHUNK];
    uchar4 ci[NVCHUNK];
    #pragma unroll
    for (int c = 0; c < NVCHUNK; c++) {
        csum += g_psum[c * NCOLS + n];
        cv[c] = g_cval[c * NCOLS + n];
        ci[c] = g_cidx[c * NCOLS + n];
    }

    float m = cv[0].x;
    #pragma unroll
    for (int c = 1; c < NVCHUNK; c++) m = fmaxf(m, cv[c].x);
    const float thr = m - g_delta[b];
    bool safe = true;
    #pragma unroll
    for (int c = 0; c < NVCHUNK; c++) safe = safe && (cv[c].w < thr);

    float best = NEG_BIG;
    int   bi   = 0;
    if (safe) {
        #pragma unroll
        for (int c = 0; c < NVCHUNK; c++) {
            const float vals[4] = {cv[c].x, cv[c].y, cv[c].z, cv[c].w};
            const int   idxs[4] = {ci[c].x, ci[c].y, ci[c].z, ci[c].w};
            #pragma unroll
            for (int k = 0; k < 4; k++) {
                const int v = c * VCHUNK + idxs[k];
                const float sc_ = vals[k] - __ldg(lse + v);
                if (sc_ > best || (sc_ == best && v < bi)) { best = sc_; bi = v; }
            }
        }
    } else {
        // exact fallback: re-read this column (rare)
        const float* colp = out + (size_t)b * BV * NS + s;
        for (int v = 0; v < BV; v++) {
            const float sc_ = __ldg(colp + (size_t)v * NS) - __ldg(lse + v);
            if (sc_ > best) { best = sc_; bi = v; }
        }
    }

    const int tgt = target[n];
    const float t_logit = __ldg(out + ((size_t)b * BV + tgt) * NS + s);
    const float nll = __logf(csum) - t_logit;

    // penalty mask
    const int   pt = __ldg(ttype  + bi), qt = __ldg(ttype  + tgt);
    const float pv = __ldg(tvalue + bi), qv = __ldg(tvalue + tgt);
    const float d  = fabsf(pv - qv);

    float pw = (d == 7.0f) ? __ldg(harm + 0)
             : (d == 5.0f) ? __ldg(harm + 1)
             : (d == 3.0f) ? __ldg(harm + 2)
             : (d == 4.0f) ? __ldg(harm + 3)
             : (d == 1.0f) ? __ldg(harm + 4)
             : (d == 2.0f) ? __ldg(harm + 5)
             :               __ldg(harm + 6);

    float w;
    if (pt != qt)       w = __ldg(coeff + 0);
    else if (pt == 0)   w = pw;
    else if (pt == 1)   w = __ldg(coeff + 1) * d * (1.0f / 160.0f);
    else if (pt == 2)   w = __ldg(coeff + 2) * d * (1.0f / 100.0f);
    else                w = __ldg(coeff + 3) * d * (1.0f / 128.0f);

    // block reduction (double), fixed order
    double dn = (double)nll, dm = (double)w;
    #pragma unroll
    for (int o = 16; o; o >>= 1) {
        dn += __shfl_down_sync(0xffffffffu, dn, o);
        dm += __shfl_down_sync(0xffffffffu, dm, o);
    }
    __shared__ double shn[TPB / 32], shm[TPB / 32];
    const int wid = threadIdx.x >> 5;
    if ((threadIdx.x & 31) == 0) { shn[wid] = dn; shm[wid] = dm; }
    __syncthreads();

    __shared__ bool s_last;
    if (threadIdx.x == 0) {
        double an = 0.0, am = 0.0;
        #pragma unroll
        for (int i = 0; i < TPB / 32; i++) { an += shn[i]; am += shm[i]; }
        g_part_nll[blockIdx.x]  = an;
        g_part_mask[blockIdx.x] = am;
        __threadfence();
        unsigned int prev = atomicAdd(&g_arrive, 1u);
        s_last = (prev == NBLKC - 1);
    }
    __syncthreads();

    if (s_last) {
        const int t = threadIdx.x;
        double an = 0.0, am = 0.0;
        #pragma unroll
        for (int k = 0; k < NBLKC / TPB; k++) {
            an += g_part_nll[t + k * TPB];
            am += g_part_mask[t + k * TPB];
        }
        #pragma unroll
        for (int o = 16; o; o >>= 1) {
            an += __shfl_down_sync(0xffffffffu, an, o);
            am += __shfl_down_sync(0xffffffffu, am, o);
        }
        if ((t & 31) == 0) { shn[t >> 5] = an; shm[t >> 5] = am; }
        __syncthreads();
        if (t == 0) {
            double fn = 0.0, fm = 0.0;
            #pragma unroll
            for (int i = 0; i < TPB / 32; i++) { fn += shn[i]; fm += shm[i]; }
            const double inv = 1.0 / (double)NCOLS;
            const double loss = fn * inv;
            res[0] = (float)(loss * (1.0 + fm * inv));
            g_arrive = 0;   // reset for next graph replay
        }
    }
}

extern "C" void kernel_launch(void* const* d_in, const int* in_sizes, int n_in,
                              void* d_out, int out_size)
{
    const float* output  = (const float*)d_in[0];   // [32, 516, 2048] f32
    const int*   target  = (const int*)  d_in[1];   // [32, 2048] i32
    const int*   ttype   = (const int*)  d_in[2];   // [516] i32
    const float* tvalue  = (const float*)d_in[3];   // [516] f32
    const float* coeff   = (const float*)d_in[4];   // [4] f32
    const float* harm    = (const float*)d_in[5];   // [7] f32
    float* out = (float*)d_out;

    k_main<<<dim3(NSCHUNK, NB, NVCHUNK), TPB>>>(output);
    k_lse<<<NB, 512>>>();
    k_comb<<<NBLKC, TPB>>>(output, target, ttype, tvalue, coeff, harm, out);
}